// round 6
// baseline (speedup 1.0000x reference)
#include <cuda_runtime.h>

#define V_SIZE 128000
#define V4 32000               // V_SIZE/4 quads
#define NWIN 125               // bcast windows of 256 quads each (V4/256)
#define R_MAX 512
#define PEN_LAMBDA 0.5f

// Scratch (__device__ globals; zero-initialized at module load).
// Invariant: every kernel_launch execution leaves all scratch back at zero
// (consume-and-reset), so graph replays are deterministic.
__device__ float g_pen[V_SIZE];
__device__ float g_pen_head[NWIN * 4];   // replica of each window's first quad
__device__ float g_firing[R_MAX];

// ---------------------------------------------------------------------------
// k_scatter: pen[token] += sigmoid(gate_logit[rule]) * lambda
// 512 threads/CTA, 1 quad (4 pairs)/thread. Gates (lambda folded) + firing
// flags in smem; firing flushed once per CTA. Tokens landing on a window's
// first quad are also added to g_pen_head (replica consumed by k_main).
// ---------------------------------------------------------------------------
__device__ __forceinline__ void scatter_one(int t, float v) {
    atomicAdd(&g_pen[t], v);
    if ((t & 1023) < 4)   // first quad of a 1024-float window
        atomicAdd(&g_pen_head[((t >> 10) << 2) | (t & 3)], v);
}

__global__ void __launch_bounds__(512) k_scatter(
    const float* __restrict__ gate_logits,
    const int* __restrict__ rule_ids,
    const int* __restrict__ token_ids,
    int n_quads)   // E/4
{
    __shared__ float s_gates[R_MAX];
    __shared__ int   s_fire[R_MAX];
    int tid = threadIdx.x;
    s_gates[tid] = PEN_LAMBDA / (1.0f + __expf(-gate_logits[tid]));
    s_fire[tid] = 0;
    __syncthreads();

    int q = blockIdx.x * 512 + tid;
    if (q < n_quads) {
        int4 r = reinterpret_cast<const int4*>(rule_ids)[q];
        int4 t = reinterpret_cast<const int4*>(token_ids)[q];
        scatter_one(t.x, s_gates[r.x]);
        scatter_one(t.y, s_gates[r.y]);
        scatter_one(t.z, s_gates[r.z]);
        scatter_one(t.w, s_gates[r.w]);
        s_fire[r.x] = 1;
        s_fire[r.y] = 1;
        s_fire[r.z] = 1;
        s_fire[r.w] = 1;
    }
    __syncthreads();
    if (s_fire[tid]) g_firing[tid] = 1.0f;   // idempotent across CTAs
}

// ---------------------------------------------------------------------------
// k_main: fused broadcast + penalties + coverage loss + scratch reset.
// 125 blocks x 256 threads; block bx owns v-quads [bx*256, bx*256+256) and
// processes ALL 64 batch rows for that window (pen staged in smem once).
// Shifted penalty quad composed from two adjacent smem quads; the window tail
// comes from g_pen_head[next window] (private replica -> no cross-block race
// with the zeroing of g_pen).
// ---------------------------------------------------------------------------
__global__ void __launch_bounds__(256) k_main(
    const float* __restrict__ logits,
    const float* __restrict__ gate_logits,
    float* __restrict__ modified,
    float* __restrict__ penalties,   // = out + BV + 1 (4B-aligned)
    float* __restrict__ out_loss)
{
    __shared__ float s_pen[1028];
    int tid = threadIdx.x;
    int bx  = blockIdx.x;
    int m0  = bx * 256;

    // stage own window + tail replica
    reinterpret_cast<float4*>(s_pen)[tid] =
        reinterpret_cast<const float4*>(g_pen)[m0 + tid];
    int wn = (bx + 1 == NWIN) ? 0 : bx + 1;
    if (tid < 4) s_pen[1024 + tid] = g_pen_head[wn * 4 + tid];
    __syncthreads();

    // consume-and-reset for next replay (this block is the sole reader)
    reinterpret_cast<float4*>(g_pen)[m0 + tid] = make_float4(0.f, 0.f, 0.f, 0.f);
    if (tid < 4) g_pen_head[wn * 4 + tid] = 0.0f;

    // coverage loss (block 0 only; block-uniform branch so __syncthreads legal)
    if (bx == 0) {
        __shared__ float sg[8], sf[8];
        float f0 = g_firing[tid], f1 = g_firing[tid + 256];
        float g0 = 1.0f / (1.0f + __expf(-gate_logits[tid]));
        float g1 = 1.0f / (1.0f + __expf(-gate_logits[tid + 256]));
        g_firing[tid] = 0.0f;           // reset after read (same thread)
        g_firing[tid + 256] = 0.0f;
        float f = f0 + f1;
        float gf = g0 * f0 + g1 * f1;
        #pragma unroll
        for (int off = 16; off > 0; off >>= 1) {
            gf += __shfl_down_sync(0xFFFFFFFF, gf, off);
            f  += __shfl_down_sync(0xFFFFFFFF, f,  off);
        }
        int warp = tid >> 5;
        if ((tid & 31) == 0) { sg[warp] = gf; sf[warp] = f; }
        __syncthreads();
        if (tid < 32) {
            float g2 = (tid < 8) ? sg[tid] : 0.0f;
            float f2 = (tid < 8) ? sf[tid] : 0.0f;
            #pragma unroll
            for (int off = 4; off > 0; off >>= 1) {
                g2 += __shfl_down_sync(0xFFFFFFFF, g2, off);
                f2 += __shfl_down_sync(0xFFFFFFFF, f2, off);
            }
            if (tid == 0) out_loss[0] = -g2 / fmaxf(f2, 1.0f);
        }
        // head/tail penalty scalars not covered by the aligned quad window
        if (tid == 0) {
            penalties[0] = s_pen[0];
            penalties[1] = s_pen[1];
            penalties[2] = s_pen[2];
        }
    }
    if (bx == NWIN - 1 && tid == 255) {
        // last penalties element: pen[V-1] == s_pen[1023] of the last window
        penalties[(int64_t)64 * V_SIZE - 1] = s_pen[1023];
    }

    float4 p  = reinterpret_cast<const float4*>(s_pen)[tid];
    float4 pn = reinterpret_cast<const float4*>(s_pen)[tid + 1];
    float4 ps = make_float4(p.w, pn.x, pn.y, pn.z);

    int m = m0 + tid;
    const float4* lg = reinterpret_cast<const float4*>(logits) + m;
    float4*       md = reinterpret_cast<float4*>(modified) + m;
    float4*       pe = reinterpret_cast<float4*>(penalties + 3) + m;
    bool last_quad = (m == V4 - 1);   // the one quad whose row-63 store overflows

    #pragma unroll 8
    for (int r = 0; r < 64; r++) {
        float4 l = __ldg(lg);
        float4 o;
        o.x = l.x - p.x; o.y = l.y - p.y; o.z = l.z - p.z; o.w = l.w - p.w;
        __stcs(md, o);
        if (!last_quad || r != 63)
            __stcs(pe, ps);
        lg += V4; md += V4; pe += V4;
    }
}

extern "C" void kernel_launch(void* const* d_in, const int* in_sizes, int n_in,
                              void* d_out, int out_size) {
    const float* logits      = (const float*)d_in[0];
    const float* gate_logits = (const float*)d_in[1];
    const int*   rule_ids    = (const int*)d_in[2];
    const int*   token_ids   = (const int*)d_in[3];

    int BV = in_sizes[0];       // 8,192,000
    int E  = in_sizes[2];       // 1,000,000

    float* out       = (float*)d_out;
    float* modified  = out;                 // [BV]
    float* out_loss  = out + BV;            // [1]
    float* penalties = out + BV + 1;        // [BV], 4B-aligned

    // 1) scatter (scratch arrives zeroed: initial state or previous k_main)
    {
        int n_quads = E / 4;                        // 250,000
        int blocks = (n_quads + 511) / 512;         // 489
        k_scatter<<<blocks, 512>>>(gate_logits, rule_ids, token_ids, n_quads);
    }
    // 2) fused broadcast + penalties + loss + scratch reset
    k_main<<<NWIN, 256>>>(logits, gate_logits, modified, penalties, out_loss);
}

// round 7
// speedup vs baseline: 1.0349x; 1.0349x over previous
#include <cuda_runtime.h>

#define V_SIZE 128000
#define V4 32000               // V_SIZE/4 quads
#define NWIN 125               // windows of 256 quads (V4/256)
#define NBY 8                  // sibling blocks per window (64 rows / 8)
#define R_MAX 512
#define PEN_LAMBDA 0.5f

// Scratch (__device__ globals; zero-initialized at load).
// Invariant: every execution leaves scratch at zero (consume-and-reset).
__device__ float g_pen[V_SIZE];
__device__ float g_pen_head[NWIN * 4];   // replica of each window's first quad
__device__ float g_firing[R_MAX];
__device__ int   g_tick[NWIN];

// ---------------------------------------------------------------------------
// k_scatter: pen[token] += sigmoid(gate_logit[rule]) * lambda
// Gates (lambda folded) + firing flags in smem; firing flushed once per CTA.
// Tokens in a window's first quad also add into g_pen_head (replica that lets
// k_main compose the +3-shifted penalty quad without cross-window hazards).
// ---------------------------------------------------------------------------
__device__ __forceinline__ void scatter_one(int t, float v) {
    atomicAdd(&g_pen[t], v);
    if ((t & 1023) < 4)
        atomicAdd(&g_pen_head[((t >> 10) << 2) | (t & 3)], v);
}

__global__ void __launch_bounds__(512) k_scatter(
    const float* __restrict__ gate_logits,
    const int* __restrict__ rule_ids,
    const int* __restrict__ token_ids,
    int n_quads)   // E/4
{
    __shared__ float s_gates[R_MAX];
    __shared__ int   s_fire[R_MAX];
    int tid = threadIdx.x;
    s_gates[tid] = PEN_LAMBDA / (1.0f + __expf(-gate_logits[tid]));
    s_fire[tid] = 0;
    __syncthreads();

    int q = blockIdx.x * 512 + tid;
    if (q < n_quads) {
        int4 r = reinterpret_cast<const int4*>(rule_ids)[q];
        int4 t = reinterpret_cast<const int4*>(token_ids)[q];
        scatter_one(t.x, s_gates[r.x]);
        scatter_one(t.y, s_gates[r.y]);
        scatter_one(t.z, s_gates[r.z]);
        scatter_one(t.w, s_gates[r.w]);
        s_fire[r.x] = 1;
        s_fire[r.y] = 1;
        s_fire[r.z] = 1;
        s_fire[r.w] = 1;
    }
    __syncthreads();
    if (s_fire[tid]) g_firing[tid] = 1.0f;   // idempotent across CTAs
}

// ---------------------------------------------------------------------------
// k_main: fused broadcast + penalties + loss + ticketed scratch reset.
// Grid (125, 8), 256 threads. Block (bx,by) covers v-quads [bx*256,+256)
// for rows [by*8, by*8+8). After staging pen to smem, each block tickets
// g_tick[bx]; the 8th arrival zeroes the window + head replica + ticket
// (all 8 readers have provably staged -> no race).
// ---------------------------------------------------------------------------
__global__ void __launch_bounds__(256) k_main(
    const float* __restrict__ logits,
    const float* __restrict__ gate_logits,
    float* __restrict__ modified,
    float* __restrict__ penalties,   // = out + BV + 1 (4B-aligned)
    float* __restrict__ out_loss,
    int pen_quads)                   // (BV-3)/4
{
    __shared__ float s_pen[1028];
    __shared__ int   s_last;
    int tid = threadIdx.x;
    int bx  = blockIdx.x;
    int m0  = bx * 256;

    // stage own window + tail replica (from next window's head copy)
    reinterpret_cast<float4*>(s_pen)[tid] =
        reinterpret_cast<const float4*>(g_pen)[m0 + tid];
    int wn = (bx + 1 == NWIN) ? 0 : bx + 1;
    if (tid < 4) s_pen[1024 + tid] = g_pen_head[wn * 4 + tid];
    __syncthreads();

    if (tid == 0)
        s_last = (atomicAdd(&g_tick[bx], 1) == NBY - 1);
    __syncthreads();
    if (s_last) {
        // all 8 sibling readers staged: safe to reset for next replay
        reinterpret_cast<float4*>(g_pen)[m0 + tid] =
            make_float4(0.f, 0.f, 0.f, 0.f);
        if (tid < 4) g_pen_head[wn * 4 + tid] = 0.0f;
        if (tid == 0) g_tick[bx] = 0;
    }

    // coverage loss: one warp of block (0,0); reads + resets g_firing
    if (bx == 0 && blockIdx.y == 0 && tid < 32) {
        float f = 0.0f, gf = 0.0f;
        #pragma unroll
        for (int k = 0; k < 16; k++) {
            int i = tid + 32 * k;
            float fi = g_firing[i];
            float gi = 1.0f / (1.0f + __expf(-gate_logits[i]));
            f += fi;
            gf += gi * fi;
            g_firing[i] = 0.0f;
        }
        #pragma unroll
        for (int off = 16; off > 0; off >>= 1) {
            gf += __shfl_down_sync(0xFFFFFFFF, gf, off);
            f  += __shfl_down_sync(0xFFFFFFFF, f,  off);
        }
        if (tid == 0) {
            out_loss[0] = -gf / fmaxf(f, 1.0f);
            // head scalars not covered by the aligned quad window
            penalties[0] = s_pen[0];
            penalties[1] = s_pen[1];
            penalties[2] = s_pen[2];
        }
    }
    if (bx == NWIN - 1 && blockIdx.y == 0 && tid == 255) {
        // last penalties element: pen[V-1] == s_pen[1023] of last window
        penalties[(int64_t)64 * V_SIZE - 1] = s_pen[1023];
    }

    float4 p  = reinterpret_cast<const float4*>(s_pen)[tid];
    float4 pn = reinterpret_cast<const float4*>(s_pen)[tid + 1];
    float4 ps = make_float4(p.w, pn.x, pn.y, pn.z);

    int m  = m0 + tid;
    int b0 = blockIdx.y * 8;
    const float4* lg = reinterpret_cast<const float4*>(logits) + (b0 * V4 + m);
    float4*       md = reinterpret_cast<float4*>(modified) + (b0 * V4 + m);
    float4*       pe = reinterpret_cast<float4*>(penalties + 3) + (b0 * V4 + m);
    int i = b0 * V4 + m;

    #pragma unroll
    for (int r = 0; r < 8; r++) {
        float4 l = __ldg(lg);
        float4 o;
        o.x = l.x - p.x; o.y = l.y - p.y; o.z = l.z - p.z; o.w = l.w - p.w;
        __stcs(md, o);
        if (i < pen_quads)
            __stcs(pe, ps);
        lg += V4; md += V4; pe += V4; i += V4;
    }
}

extern "C" void kernel_launch(void* const* d_in, const int* in_sizes, int n_in,
                              void* d_out, int out_size) {
    const float* logits      = (const float*)d_in[0];
    const float* gate_logits = (const float*)d_in[1];
    const int*   rule_ids    = (const int*)d_in[2];
    const int*   token_ids   = (const int*)d_in[3];

    int BV = in_sizes[0];       // 8,192,000
    int E  = in_sizes[2];       // 1,000,000

    float* out       = (float*)d_out;
    float* modified  = out;                 // [BV]
    float* out_loss  = out + BV;            // [1]
    float* penalties = out + BV + 1;        // [BV], 4B-aligned

    // 1) scatter (scratch arrives zeroed: initial state or previous k_main)
    {
        int n_quads = E / 4;                        // 250,000
        int blocks = (n_quads + 511) / 512;         // 489
        k_scatter<<<blocks, 512>>>(gate_logits, rule_ids, token_ids, n_quads);
    }
    // 2) fused broadcast + penalties + loss + ticketed reset
    {
        int pen_quads = (BV - 3) / 4;               // 2,047,999
        dim3 grid(NWIN, NBY);                       // (125, 8)
        k_main<<<grid, 256>>>(logits, gate_logits, modified, penalties,
                              out_loss, pen_quads);
    }
}

// round 9
// speedup vs baseline: 1.1616x; 1.1225x over previous
#include <cuda_runtime.h>

#define V_SIZE 128000
#define V4 32000               // V_SIZE/4 quads
#define NWIN 125               // windows of 256 quads (V4/256)
#define NBY 8                  // sibling blocks per window (64 rows / 8)
#define R_MAX 512
#define PEN_LAMBDA 0.5f

// Scratch (__device__ globals; zero-initialized at load).
// Invariant: every execution leaves scratch at zero (consume-and-reset).
__device__ float g_pen[V_SIZE];
__device__ float g_pen_head[NWIN * 4];   // replica of each window's first quad
__device__ float g_firing[R_MAX];
__device__ int   g_tick[NWIN];

// ---------------------------------------------------------------------------
// k_scatter: pen[token] += sigmoid(gate_logit[rule]) * lambda
// 245 blocks x 512 threads, 2 quads (8 pairs)/thread. Gates (lambda folded)
// + firing flags in smem; firing flushed once per CTA. Tokens in a window's
// first quad also add into g_pen_head (replica consumed by k_main).
// ---------------------------------------------------------------------------
__device__ __forceinline__ void scatter_one(int t, float v) {
    atomicAdd(&g_pen[t], v);
    if ((t & 1023) < 4)
        atomicAdd(&g_pen_head[((t >> 10) << 2) | (t & 3)], v);
}

__global__ void __launch_bounds__(512) k_scatter(
    const float* __restrict__ gate_logits,
    const int* __restrict__ rule_ids,
    const int* __restrict__ token_ids,
    int n_quads)   // E/4
{
    __shared__ float s_gates[R_MAX];
    __shared__ int   s_fire[R_MAX];
    int tid = threadIdx.x;
    s_gates[tid] = PEN_LAMBDA / (1.0f + __expf(-gate_logits[tid]));
    s_fire[tid] = 0;
    __syncthreads();

    #pragma unroll
    for (int p = 0; p < 2; p++) {
        int q = blockIdx.x * 1024 + p * 512 + tid;
        if (q < n_quads) {
            int4 r = reinterpret_cast<const int4*>(rule_ids)[q];
            int4 t = reinterpret_cast<const int4*>(token_ids)[q];
            scatter_one(t.x, s_gates[r.x]);
            scatter_one(t.y, s_gates[r.y]);
            scatter_one(t.z, s_gates[r.z]);
            scatter_one(t.w, s_gates[r.w]);
            s_fire[r.x] = 1;
            s_fire[r.y] = 1;
            s_fire[r.z] = 1;
            s_fire[r.w] = 1;
        }
    }
    __syncthreads();
    if (s_fire[tid]) g_firing[tid] = 1.0f;   // idempotent across CTAs
}

// ---------------------------------------------------------------------------
// k_main: fused broadcast + penalties + loss + deferred ticketed reset.
// Grid (125, 8), 256 threads. Block (bx,by): v-quads [bx*256,+256) for rows
// [by*8,+8). Critical path = stage -> sync -> batched loop. Ticket atomic is
// issued right after staging (latency hidden by the loop); the 8th-arriving
// sibling zeroes the window + head replica + ticket AFTER its loop.
// ---------------------------------------------------------------------------
__global__ void __launch_bounds__(256) k_main(
    const float* __restrict__ logits,
    const float* __restrict__ gate_logits,
    float* __restrict__ modified,
    float* __restrict__ penalties,   // = out + BV + 1 (4B-aligned)
    float* __restrict__ out_loss,
    int pen_quads)                   // (BV-3)/4
{
    __shared__ float s_pen[1028];
    __shared__ int   s_last;
    int tid = threadIdx.x;
    int bx  = blockIdx.x;
    int m0  = bx * 256;
    int wn  = (bx + 1 == NWIN) ? 0 : bx + 1;

    // stage own window + tail replica (from next window's head copy)
    reinterpret_cast<float4*>(s_pen)[tid] =
        reinterpret_cast<const float4*>(g_pen)[m0 + tid];
    if (tid < 4) s_pen[1024 + tid] = g_pen_head[wn * 4 + tid];
    __syncthreads();

    // ticket "I have staged" — result consumed only after the main loop
    if (tid == 0)
        s_last = (atomicAdd(&g_tick[bx], 1) == NBY - 1);

    // coverage loss: one warp of block (0,0); reads + resets g_firing
    if (bx == 0 && blockIdx.y == 0 && tid >= 32 && tid < 64) {
        int lt = tid - 32;
        float f = 0.0f, gf = 0.0f;
        #pragma unroll
        for (int k = 0; k < 16; k++) {
            int i = lt + 32 * k;
            float fi = g_firing[i];
            float gi = 1.0f / (1.0f + __expf(-gate_logits[i]));
            f += fi;
            gf += gi * fi;
            g_firing[i] = 0.0f;
        }
        #pragma unroll
        for (int off = 16; off > 0; off >>= 1) {
            gf += __shfl_down_sync(0xFFFFFFFF, gf, off);
            f  += __shfl_down_sync(0xFFFFFFFF, f,  off);
        }
        if (lt == 0) {
            out_loss[0] = -gf / fmaxf(f, 1.0f);
            penalties[0] = s_pen[0];
            penalties[1] = s_pen[1];
            penalties[2] = s_pen[2];
        }
    }
    if (bx == NWIN - 1 && blockIdx.y == 0 && tid == 255) {
        penalties[(int64_t)64 * V_SIZE - 1] = s_pen[1023];
    }

    float4 p  = reinterpret_cast<const float4*>(s_pen)[tid];
    float4 pn = reinterpret_cast<const float4*>(s_pen)[tid + 1];
    float4 ps = make_float4(p.w, pn.x, pn.y, pn.z);

    int m  = m0 + tid;
    int i0 = blockIdx.y * 8 * V4 + m;
    const float4* lg = reinterpret_cast<const float4*>(logits) + i0;
    float4*       md = reinterpret_cast<float4*>(modified) + i0;
    float4*       pe = reinterpret_cast<float4*>(penalties + 3) + i0;

    // front-batched loads: 8 LDG.128 in flight before any compute/store
    float4 l[8];
    #pragma unroll
    for (int r = 0; r < 8; r++)
        l[r] = __ldg(lg + r * V4);

    #pragma unroll
    for (int r = 0; r < 8; r++) {
        float4 o;
        o.x = l[r].x - p.x; o.y = l[r].y - p.y;
        o.z = l[r].z - p.z; o.w = l[r].w - p.w;
        __stcs(md + r * V4, o);
        if (i0 + r * V4 < pen_quads)
            __stcs(pe + r * V4, ps);
    }

    // deferred reset by the last-arriving sibling
    __syncthreads();
    if (s_last) {
        reinterpret_cast<float4*>(g_pen)[m0 + tid] =
            make_float4(0.f, 0.f, 0.f, 0.f);
        if (tid < 4) g_pen_head[wn * 4 + tid] = 0.0f;
        if (tid == 0) g_tick[bx] = 0;
    }
}

extern "C" void kernel_launch(void* const* d_in, const int* in_sizes, int n_in,
                              void* d_out, int out_size) {
    const float* logits      = (const float*)d_in[0];
    const float* gate_logits = (const float*)d_in[1];
    const int*   rule_ids    = (const int*)d_in[2];
    const int*   token_ids   = (const int*)d_in[3];

    int BV = in_sizes[0];       // 8,192,000
    int E  = in_sizes[2];       // 1,000,000

    float* out       = (float*)d_out;
    float* modified  = out;                 // [BV]
    float* out_loss  = out + BV;            // [1]
    float* penalties = out + BV + 1;        // [BV], 4B-aligned

    // 1) scatter (scratch arrives zeroed: initial state or previous k_main)
    {
        int n_quads = E / 4;                        // 250,000
        int blocks = (n_quads + 1023) / 1024;       // 245
        k_scatter<<<blocks, 512>>>(gate_logits, rule_ids, token_ids, n_quads);
    }
    // 2) fused broadcast + penalties + loss + deferred reset
    {
        int pen_quads = (BV - 3) / 4;               // 2,047,999
        dim3 grid(NWIN, NBY);                       // (125, 8)
        k_main<<<grid, 256>>>(logits, gate_logits, modified, penalties,
                              out_loss, pen_quads);
    }
}